// round 3
// baseline (speedup 1.0000x reference)
#include <cuda_runtime.h>
#include <math.h>

#define BB 16
#define HH 384
#define WW 384
#define NPIX (BB * HH * WW)
#define NWORDS 12               // 384 / 32
#define RPB 4                   // rows per block in kernel 1

// Scratch: horizontal nearest-fg distance g per pixel, uint16 (g <= 768).
__device__ __align__(16) unsigned short g_g[NPIX];

// ---------------------------------------------------------------------------
// Kernel 1: per-row 1D distance to nearest foreground pixel (exact).
// 384 threads, 4 rows/block. Load phase: each thread loads int4 (4 cols) and
// ORs a 4-bit nibble into a shared row bitmask (12 words/row). Compute phase:
// thread j finds nearest set bit via clz/ffs (word-scan fallback exact).
// No-fg row -> g = BIG = 768 (matches reference clip). Zeroes out[0].
// ---------------------------------------------------------------------------
__global__ void row_dist_kernel(const int* __restrict__ targets,
                                float* __restrict__ out) {
    __shared__ unsigned smask[RPB][NWORDS];
    const int tid = threadIdx.x;                    // 0..383
    const int row0 = blockIdx.x * RPB;

    if (blockIdx.x == 0 && tid == 0) out[0] = 0.0f;

    if (tid < RPB * NWORDS) ((unsigned*)smask)[tid] = 0u;
    __syncthreads();

    // Build fg bitmasks: thread -> (row k, quad q) = cols 4q..4q+3
    {
        const int k = tid / 96;
        const int q = tid % 96;
        const int4 t4 = *(const int4*)(targets + (size_t)(row0 + k) * WW + q * 4);
        const unsigned nib = (unsigned)(t4.x != 0)
                           | ((unsigned)(t4.y != 0) << 1)
                           | ((unsigned)(t4.z != 0) << 2)
                           | ((unsigned)(t4.w != 0) << 3);
        if (nib) atomicOr(&smask[k][q >> 3], nib << ((q & 7) * 4));
    }
    __syncthreads();

    const int j = tid;
    const int wj = j >> 5;
    const int bj = j & 31;

    #pragma unroll
    for (int k = 0; k < RPB; ++k) {
        const unsigned* mask = smask[k];
        const unsigned own = mask[wj];

        // nearest set bit at position <= j
        int dl;
        const unsigned ml = own & (0xFFFFFFFFu >> (31 - bj));
        if (ml) {
            dl = bj - (31 - __clz(ml));
        } else {
            dl = 0x7FFFFF;
            for (int w = wj - 1; w >= 0; --w) {
                const unsigned m = mask[w];
                if (m) { dl = j - (w * 32 + 31 - __clz(m)); break; }
            }
        }

        // nearest set bit at position >= j
        int dr;
        const unsigned mr = own & (0xFFFFFFFFu << bj);
        if (mr) {
            dr = (__ffs(mr) - 1) - bj;
        } else {
            dr = 0x7FFFFF;
            for (int w = wj + 1; w < NWORDS; ++w) {
                const unsigned m = mask[w];
                if (m) { dr = (w * 32 + __ffs(m) - 1) - j; break; }
            }
        }

        int d = min(dl, dr);
        d = min(d, 768);                            // BIG = H + W (no-fg row)
        g_g[(size_t)(row0 + k) * WW + j] = (unsigned short)d;
    }
}

// ---------------------------------------------------------------------------
// Kernel 2: exact vertical lower-envelope min (bounded outward search) fused
// with sigmoid, |p-t|, sqrt, block reduction, scaled atomicAdd into out.
// 4 columns/thread; each search iteration loads ONE uint2 (4 x u16 g values)
// per side, converts, and fmaf's g*g + r^2. targets are NOT read: t == (g==0).
// Early exit when r^2 >= max(best0..3) is exact.
// ---------------------------------------------------------------------------
__global__ void loss_kernel(const float* __restrict__ logits,
                            float* __restrict__ out) {
    const int tid = blockIdx.x * blockDim.x + threadIdx.x;   // < NPIX/4
    const int base = tid * 4;
    const int j = base % WW;                  // multiple of 4 -> 8B aligned u16x4
    const int i = (base / WW) % HH;
    const int b = base / (WW * HH);

    const unsigned short* gimg = g_g + (size_t)b * HH * WW;

    const uint2 ow = *(const uint2*)(gimg + i * WW + j);
    const unsigned go0 = ow.x & 0xFFFFu, go1 = ow.x >> 16;
    const unsigned go2 = ow.y & 0xFFFFu, go3 = ow.y >> 16;
    const float f0 = (float)go0, f1 = (float)go1, f2 = (float)go2, f3 = (float)go3;
    float best0 = f0 * f0, best1 = f1 * f1, best2 = f2 * f2, best3 = f3 * f3;
    float bmax = fmaxf(fmaxf(best0, best1), fmaxf(best2, best3));

    #pragma unroll 1
    for (int r = 1; r < HH; ++r) {
        const float r2 = (float)(r * r);
        if (r2 >= bmax) break;
        if (i - r >= 0) {
            const uint2 u = *(const uint2*)(gimg + (i - r) * WW + j);
            const float a0 = (float)(u.x & 0xFFFFu), a1 = (float)(u.x >> 16);
            const float a2 = (float)(u.y & 0xFFFFu), a3 = (float)(u.y >> 16);
            best0 = fminf(best0, fmaf(a0, a0, r2));
            best1 = fminf(best1, fmaf(a1, a1, r2));
            best2 = fminf(best2, fmaf(a2, a2, r2));
            best3 = fminf(best3, fmaf(a3, a3, r2));
        }
        if (i + r < HH) {
            const uint2 v = *(const uint2*)(gimg + (i + r) * WW + j);
            const float c0 = (float)(v.x & 0xFFFFu), c1 = (float)(v.x >> 16);
            const float c2 = (float)(v.y & 0xFFFFu), c3 = (float)(v.y >> 16);
            best0 = fminf(best0, fmaf(c0, c0, r2));
            best1 = fminf(best1, fmaf(c1, c1, r2));
            best2 = fminf(best2, fmaf(c2, c2, r2));
            best3 = fminf(best3, fmaf(c3, c3, r2));
        }
        bmax = fmaxf(fmaxf(best0, best1), fmaxf(best2, best3));
    }

    const float4 lg = *(const float4*)(logits + base);

    // target bit recovered from horizontal distance: t == 1 <=> g == 0
    const float t0 = (go0 == 0u) ? 1.0f : 0.0f;
    const float t1 = (go1 == 0u) ? 1.0f : 0.0f;
    const float t2 = (go2 == 0u) ? 1.0f : 0.0f;
    const float t3 = (go3 == 0u) ? 1.0f : 0.0f;

    float val;
    {
        const float p0 = 1.0f / (1.0f + __expf(-lg.x));
        const float p1 = 1.0f / (1.0f + __expf(-lg.y));
        const float p2 = 1.0f / (1.0f + __expf(-lg.z));
        const float p3 = 1.0f / (1.0f + __expf(-lg.w));
        val  = fabsf(p0 - t0) * sqrtf(best0);
        val += fabsf(p1 - t1) * sqrtf(best1);
        val += fabsf(p2 - t2) * sqrtf(best2);
        val += fabsf(p3 - t3) * sqrtf(best3);
    }

    // Warp + block reduction, then one scaled atomic per block
    #pragma unroll
    for (int off = 16; off > 0; off >>= 1)
        val += __shfl_xor_sync(0xFFFFFFFFu, val, off);

    __shared__ float warp_sums[8];                  // 256 threads = 8 warps
    const int lane = threadIdx.x & 31;
    const int wid = threadIdx.x >> 5;
    if (lane == 0) warp_sums[wid] = val;
    __syncthreads();
    if (wid == 0) {
        float s = (lane < (blockDim.x >> 5)) ? warp_sums[lane] : 0.0f;
        #pragma unroll
        for (int off = 4; off > 0; off >>= 1)
            s += __shfl_xor_sync(0xFFFFFFFFu, s, off);
        if (lane == 0) atomicAdd(out, s * (1.0f / (float)NPIX));
    }
}

extern "C" void kernel_launch(void* const* d_in, const int* in_sizes, int n_in,
                              void* d_out, int out_size) {
    const float* logits = (const float*)d_in[0];
    const int* targets = (const int*)d_in[1];
    float* out = (float*)d_out;

    (void)in_sizes; (void)n_in; (void)out_size;

    // 1) Horizontal distances (u16) + out zeroing
    row_dist_kernel<<<(BB * HH) / RPB, WW>>>(targets, out);

    // 2) Vertical envelope + loss + reduction
    const int threads = 256;
    const int blocks = (NPIX / 4) / threads;        // 2304
    loss_kernel<<<blocks, threads>>>(logits, out);
}